// round 14
// baseline (speedup 1.0000x reference)
#include <cuda_runtime.h>
#include <cuda_fp16.h>
#include <cstdint>
#include <math.h>

// ---------------- problem constants ----------------
#define NN    100000
#define EE    1600000
#define DIN   256
#define DOUT  64
#define KPROP 10
#define ALPHA 0.1f

// ---------------- static device scratch ----------------
__device__ __half g_hh [(size_t)NN * DOUT];   // h in fp16
__device__ __half g_zhA[(size_t)NN * DOUT];
__device__ __half g_zhB[(size_t)NN * DOUT];
__device__ float  g_dinv[NN];

__device__ int   g_cnt   [NN];
__device__ int   g_cursor[NN];
__device__ int   g_rowstart[NN + 1];
__device__ int2  g_epk[EE + 16];     // packed (src idx, weight bits)
__device__ int   g_blksum[128];
__device__ int   g_blkoff[128];
__device__ volatile unsigned g_bar_count;

#define SCAN_BS  1024
#define SCAN_NB  ((NN + SCAN_BS - 1) / SCAN_BS)   // 98
__device__ int g_rowtmp[NN];

// ---------------- helpers ----------------
__device__ __forceinline__ uint32_t f2h2(float a, float b) {
    __half2 h = __floats2half2_rn(a, b);
    return *(uint32_t*)&h;
}

__device__ __forceinline__ uint32_t ldcg_u32(const void* p) {
    uint32_t v;
    asm volatile("ld.global.cg.u32 %0, [%1];" : "=r"(v) : "l"(p));
    return v;
}

__device__ __forceinline__ float2 h2bits_to_f2(uint32_t bits) {
    __half2 h = *(__half2*)&bits;
    return __half22float2(h);
}

__device__ __forceinline__ void mma_16816(float* c, const uint32_t* a,
                                          uint32_t b0, uint32_t b1) {
    asm volatile(
        "mma.sync.aligned.m16n8k16.row.col.f32.f16.f16.f32 "
        "{%0,%1,%2,%3}, {%4,%5,%6,%7}, {%8,%9}, {%0,%1,%2,%3};"
        : "+f"(c[0]), "+f"(c[1]), "+f"(c[2]), "+f"(c[3])
        : "r"(a[0]), "r"(a[1]), "r"(a[2]), "r"(a[3]), "r"(b0), "r"(b1));
}

__device__ __forceinline__ void ldsm_x4(uint32_t* r, uint32_t addr) {
    asm volatile("ldmatrix.sync.aligned.m8n8.x4.shared.b16 {%0,%1,%2,%3}, [%4];"
                 : "=r"(r[0]), "=r"(r[1]), "=r"(r[2]), "=r"(r[3]) : "r"(addr));
}

// ---------------- tensor-core GEMM + bias + ReLU (R8-proven) -----------
#define GROWS 128
#define XPAD  72   // half stride; row pitch 144B

__global__ __launch_bounds__(256) void gemm_relu(
    const float* __restrict__ x, const float* __restrict__ W,
    const float* __restrict__ b)
{
    __shared__ __half xs[GROWS * XPAD];   // 18.4 KB
    __shared__ __half ws[DOUT * XPAD];    //  9.2 KB

    const int tid  = threadIdx.x;
    const int warp = tid >> 5;
    const int lane = tid & 31;
    const int gid  = lane >> 2;
    const int tg   = lane & 3;
    const int row0 = blockIdx.x * GROWS;
    const int wrow = warp * 16;

    const uint32_t xs_base = (uint32_t)__cvta_generic_to_shared(xs);
    const uint32_t ws_base = (uint32_t)__cvta_generic_to_shared(ws);

    const int arow    = wrow + (lane & 15);
    const int acolsel = (lane >> 4) << 3;
    const int browsel = (((lane >> 4) & 1) << 3) + (lane & 7);
    const int bcolsel = ((lane >> 3) & 1) << 3;

    float acc[8][4];
#pragma unroll
    for (int nt = 0; nt < 8; nt++)
#pragma unroll
        for (int q = 0; q < 4; q++) acc[nt][q] = 0.f;

    for (int kc = 0; kc < DIN / 64; kc++) {
        const int k0 = kc * 64;
        __syncthreads();
        {
            int n  = tid >> 2;
            int kq = (tid & 3) * 16;
            const float4* wsrc = (const float4*)(W + (size_t)n * DIN + k0 + kq);
            uint4* d = (uint4*)&ws[n * XPAD + kq];
#pragma unroll
            for (int i = 0; i < 2; i++) {
                float4 v0 = wsrc[2 * i], v1 = wsrc[2 * i + 1];
                uint4 u;
                u.x = f2h2(v0.x, v0.y); u.y = f2h2(v0.z, v0.w);
                u.z = f2h2(v1.x, v1.y); u.w = f2h2(v1.z, v1.w);
                d[i] = u;
            }
        }
        {
            int r  = tid >> 1;
            int kq = (tid & 1) * 32;
            int gr = row0 + r;
            uint4* d = (uint4*)&xs[r * XPAD + kq];
            if (gr < NN) {
                const float4* xsrc = (const float4*)(x + (size_t)gr * DIN + k0 + kq);
#pragma unroll
                for (int i = 0; i < 4; i++) {
                    float4 v0 = xsrc[2 * i], v1 = xsrc[2 * i + 1];
                    uint4 u;
                    u.x = f2h2(v0.x, v0.y); u.y = f2h2(v0.z, v0.w);
                    u.z = f2h2(v1.x, v1.y); u.w = f2h2(v1.z, v1.w);
                    d[i] = u;
                }
            } else {
                uint4 u = make_uint4(0, 0, 0, 0);
#pragma unroll
                for (int i = 0; i < 4; i++) d[i] = u;
            }
        }
        __syncthreads();

#pragma unroll
        for (int ks = 0; ks < 4; ks++) {
            uint32_t a[4];
            ldsm_x4(a, xs_base + (uint32_t)((arow * XPAD + ks * 16 + acolsel) * 2));
#pragma unroll
            for (int p = 0; p < 4; p++) {
                uint32_t bb[4];
                int brow = p * 16 + browsel;
                ldsm_x4(bb, ws_base + (uint32_t)((brow * XPAD + ks * 16 + bcolsel) * 2));
                mma_16816(acc[2 * p],     a, bb[0], bb[1]);
                mma_16816(acc[2 * p + 1], a, bb[2], bb[3]);
            }
        }
    }

    int r0 = row0 + wrow + gid;
    int r1 = r0 + 8;
#pragma unroll
    for (int nt = 0; nt < 8; nt++) {
        int cn = nt * 8 + 2 * tg;
        float b0v = b[cn], b1v = b[cn + 1];
        int ci = (cn >> 1);
        if (r0 < NN) {
            __half2 v = __floats2half2_rn(fmaxf(acc[nt][0] + b0v, 0.f),
                                          fmaxf(acc[nt][1] + b1v, 0.f));
            ((__half2*)g_hh )[r0 * 32 + ci] = v;
            ((__half2*)g_zhA)[r0 * 32 + ci] = v;
        }
        if (r1 < NN) {
            __half2 v = __floats2half2_rn(fmaxf(acc[nt][2] + b0v, 0.f),
                                          fmaxf(acc[nt][3] + b1v, 0.f));
            ((__half2*)g_hh )[r1 * 32 + ci] = v;
            ((__half2*)g_zhA)[r1 * 32 + ci] = v;
        }
    }
}

// ---------------- degree count + scan + CSR ----------------
__global__ void cnt_init() {
    int i = blockIdx.x * blockDim.x + threadIdx.x;
    if (i < NN) { g_cnt[i] = 0; g_cursor[i] = 0; }
    if (i == 0) g_bar_count = 0;
}

__global__ void deg_acc(const int* __restrict__ dst) {
    int e = blockIdx.x * blockDim.x + threadIdx.x;
    if (e < EE) atomicAdd(&g_cnt[dst[e]], 1);
}

__global__ __launch_bounds__(256) void scanA() {
    __shared__ int sh[256];
    int tid  = threadIdx.x;
    int base = blockIdx.x * SCAN_BS + tid * 4;
    int v[4];
#pragma unroll
    for (int q = 0; q < 4; q++) {
        int idx = base + q;
        v[q] = (idx < NN) ? g_cnt[idx] : 0;
        if (idx < NN) g_dinv[idx] = rsqrtf((float)(v[q] + 1));
    }
    int tsum = v[0] + v[1] + v[2] + v[3];
    sh[tid] = tsum;
    __syncthreads();
    for (int off = 1; off < 256; off <<= 1) {
        int x = (tid >= off) ? sh[tid - off] : 0;
        __syncthreads();
        sh[tid] += x;
        __syncthreads();
    }
    int run = sh[tid] - tsum;
#pragma unroll
    for (int q = 0; q < 4; q++) {
        int idx = base + q;
        if (idx < NN) g_rowtmp[idx] = run;
        run += v[q];
    }
    if (tid == 255) g_blksum[blockIdx.x] = sh[255];
}

__global__ __launch_bounds__(128) void scanB() {
    __shared__ int sh[128];
    int tid = threadIdx.x;
    int v = (tid < SCAN_NB) ? g_blksum[tid] : 0;
    sh[tid] = v;
    __syncthreads();
    for (int off = 1; off < 128; off <<= 1) {
        int x = (tid >= off) ? sh[tid - off] : 0;
        __syncthreads();
        sh[tid] += x;
        __syncthreads();
    }
    g_blkoff[tid] = sh[tid] - v;
}

__global__ void scanC() {
    int i = blockIdx.x * blockDim.x + threadIdx.x;
    if (i < NN) g_rowstart[i] = g_rowtmp[i] + g_blkoff[i / SCAN_BS];
    if (i == 0) g_rowstart[NN] = EE;
}

__global__ void csr_fill(const int* __restrict__ src, const int* __restrict__ dst) {
    int e = blockIdx.x * blockDim.x + threadIdx.x;
    if (e >= EE) return;
    int d = dst[e];
    int s = src[e];
    int pos = g_rowstart[d] + atomicAdd(&g_cursor[d], 1);
    float w = 0.9f * g_dinv[s] * g_dinv[d];
    g_epk[pos] = make_int2(s, __float_as_int(w));
}

// ---------------- persistent APPNP: all K steps, one kernel ------------
// grid = SMs*4, __launch_bounds__(256,4) guarantees co-residency (regs<=64).
// z gathers use ld.global.cg (L2) -- L1 is not coherent across SMs and is
// NOT flushed between steps here. Read-only data (epk/rowstart/hh/dinv)
// stays L1-cached across steps (same block -> same nodes every step).
#define WPB 8
#define NVIRT ((NN + WPB - 1) / WPB)   // 12500

__global__ __launch_bounds__(256, 4) void appnp_persist(float* __restrict__ ext) {
    const int warp = threadIdx.x >> 5;
    const int lane = threadIdx.x & 31;

    for (int step = 0; step < KPROP; step++) {
        const __half* zin = (step & 1) ? g_zhB : g_zhA;
        __half*      zoh  = (step & 1) ? g_zhA : g_zhB;
        const bool   last = (step == KPROP - 1);

        for (int vb = blockIdx.x; vb < NVIRT; vb += gridDim.x) {
            int node = vb * WPB + warp;
            if (node >= NN) continue;

            float di = g_dinv[node];
            float sw = 0.9f * di * di;
            int   ri = node * 32 + lane;

            float2 hd = __half22float2(((const __half2*)g_hh)[ri]);
            float2 zd = h2bits_to_f2(ldcg_u32((const __half2*)zin + ri));
            float accx = ALPHA * hd.x + sw * zd.x;
            float accy = ALPHA * hd.y + sw * zd.y;

            int j  = g_rowstart[node];
            int j1 = g_rowstart[node + 1];

            for (; j + 8 <= j1; j += 8) {
                int2 p[8];
#pragma unroll
                for (int q = 0; q < 8; q++) p[q] = g_epk[j + q];
                float2 a[8];
#pragma unroll
                for (int q = 0; q < 8; q++)
                    a[q] = h2bits_to_f2(ldcg_u32((const __half2*)zin + p[q].x * 32 + lane));
#pragma unroll
                for (int q = 0; q < 8; q++) {
                    float w = __int_as_float(p[q].y);
                    accx += w * a[q].x;
                    accy += w * a[q].y;
                }
            }
            for (; j < j1; j++) {
                int2  p = g_epk[j];
                float w = __int_as_float(p.y);
                float2 a = h2bits_to_f2(ldcg_u32((const __half2*)zin + p.x * 32 + lane));
                accx += w * a.x;
                accy += w * a.y;
            }

            if (last) {
                float2 o; o.x = accx; o.y = accy;
                ((float2*)ext)[ri] = o;
            } else {
                ((__half2*)zoh)[ri] = __floats2half2_rn(accx, accy);
            }
        }

        // grid-wide barrier between steps
        if (!last) {
            __syncthreads();
            if (threadIdx.x == 0) {
                __threadfence();
                atomicAdd((unsigned*)&g_bar_count, 1u);
                unsigned tgt = (unsigned)(step + 1) * gridDim.x;
                while (g_bar_count < tgt) __nanosleep(40);
            }
            __syncthreads();
        }
    }
}

// ---------------- launch (forked graph: GEMM || CSR build) -------------
extern "C" void kernel_launch(void* const* d_in, const int* in_sizes, int n_in,
                              void* d_out, int out_size) {
    const float* x  = (const float*)d_in[0];
    const int*   ei = (const int*)  d_in[1];
    const float* W  = (const float*)d_in[2];
    const float* b  = (const float*)d_in[3];
    float* out = (float*)d_out;

    const int* se = ei;        // src row
    const int* de = ei + EE;   // dst row

    static cudaStream_t s2 = nullptr;
    static cudaEvent_t  evFork = nullptr, evJoin = nullptr;
    static int pgrid = 0;
    if (s2 == nullptr) {
        cudaStreamCreateWithFlags(&s2, cudaStreamNonBlocking);
        cudaEventCreateWithFlags(&evFork, cudaEventDisableTiming);
        cudaEventCreateWithFlags(&evJoin, cudaEventDisableTiming);
        int smc = 0;
        cudaDeviceGetAttribute(&smc, cudaDevAttrMultiProcessorCount, 0);
        if (smc <= 0) smc = 132;           // conservative fallback
        pgrid = smc * 4;                   // guaranteed co-resident
    }

    // fork: GEMM on s2, concurrent with CSR build chain
    cudaEventRecord(evFork, 0);
    cudaStreamWaitEvent(s2, evFork, 0);
    gemm_relu<<<(NN + GROWS - 1) / GROWS, 256, 0, s2>>>(x, W, b);
    cudaEventRecord(evJoin, s2);

    cnt_init<<<(NN + 255) / 256, 256>>>();
    deg_acc<<<(EE + 255) / 256, 256>>>(de);
    scanA<<<SCAN_NB, 256>>>();
    scanB<<<1, 128>>>();
    scanC<<<(NN + 255) / 256, 256>>>();
    csr_fill<<<(EE + 255) / 256, 256>>>(se, de);

    cudaStreamWaitEvent(0, evJoin, 0);

    // all K propagation steps in one persistent kernel
    appnp_persist<<<pgrid, WPB * 32>>>(out);
}

// round 16
// speedup vs baseline: 1.2208x; 1.2208x over previous
#include <cuda_runtime.h>
#include <cuda_fp16.h>
#include <cstdint>
#include <math.h>

// ---------------- problem constants ----------------
#define NN    100000
#define EE    1600000
#define DIN   256
#define DOUT  64
#define KPROP 10
#define ALPHA 0.1f

// ---------------- static device scratch ----------------
__device__ __half g_hh [(size_t)NN * DOUT];   // h in fp16
__device__ __half g_zhA[(size_t)NN * DOUT];
__device__ __half g_zhB[(size_t)NN * DOUT];
__device__ float  g_dinv[NN];

__device__ int   g_cnt   [NN];
__device__ int   g_cursor[NN];
__device__ int   g_rowstart[NN + 1];
__device__ int2  g_epk[EE + 16];     // packed (src idx, weight bits)
__device__ int   g_blksum[128];
__device__ int   g_blkoff[128];

#define SCAN_BS  1024
#define SCAN_NB  ((NN + SCAN_BS - 1) / SCAN_BS)   // 98
__device__ int g_rowtmp[NN];

// ---------------- helpers ----------------
__device__ __forceinline__ uint32_t f2h2(float a, float b) {
    __half2 h = __floats2half2_rn(a, b);
    return *(uint32_t*)&h;
}

__device__ __forceinline__ void mma_16816(float* c, const uint32_t* a,
                                          uint32_t b0, uint32_t b1) {
    asm volatile(
        "mma.sync.aligned.m16n8k16.row.col.f32.f16.f16.f32 "
        "{%0,%1,%2,%3}, {%4,%5,%6,%7}, {%8,%9}, {%0,%1,%2,%3};"
        : "+f"(c[0]), "+f"(c[1]), "+f"(c[2]), "+f"(c[3])
        : "r"(a[0]), "r"(a[1]), "r"(a[2]), "r"(a[3]), "r"(b0), "r"(b1));
}

__device__ __forceinline__ void cp_async16(uint32_t dst, const void* src, int sz) {
    asm volatile("cp.async.cg.shared.global [%0], [%1], 16, %2;"
                 :: "r"(dst), "l"(src), "r"(sz));
}

// ---------------- cp.async pipelined tensor-core GEMM ------------------
// h = relu(x @ W^T + b) -> g_hh, g_zhA (fp16). fp32 staged via LDGSTS,
// fragments built by LDS.64 + pack from fp32 smem. 2-stage pipeline.
#define GROWS 128
#define KC2   32
#define XSTR  36   // padded fp32 stride (144B rows, 16B-aligned)
#define GEMM_SMEM ((2 * GROWS * XSTR + 2 * DOUT * XSTR) * 4)   // 55296 B

__global__ __launch_bounds__(256) void gemm_relu(
    const float* __restrict__ x, const float* __restrict__ W,
    const float* __restrict__ b)
{
    extern __shared__ float smem_dyn[];
    float* sx = smem_dyn;                    // [2][128][36]
    float* sw = smem_dyn + 2 * GROWS * XSTR; // [2][64][36]
    const uint32_t sx_base = (uint32_t)__cvta_generic_to_shared(sx);
    const uint32_t sw_base = (uint32_t)__cvta_generic_to_shared(sw);

    const int tid  = threadIdx.x;
    const int warp = tid >> 5;
    const int lane = tid & 31;
    const int gid  = lane >> 2;     // 0..7
    const int tg   = lane & 3;      // 0..3
    const int row0 = blockIdx.x * GROWS;
    const int wrow = warp * 16;

    // loader roles
    const int  xr  = tid >> 1;              // 0..127
    const int  xfo = (tid & 1) * 16;        // float offset in chunk
    const int  wn  = tid & 63;              // 0..63
    const int  wfo = (tid >> 6) * 8;        // 0,8,16,24
    const int  xgr = row0 + xr;
    const bool xok = (xgr < NN);
    const float* xrow_src = xok ? (x + (size_t)xgr * DIN) : x;
    const int  xsz = xok ? 16 : 0;
    const float* wrow_src = W + (size_t)wn * DIN;

    float acc[8][4];
#pragma unroll
    for (int nt = 0; nt < 8; nt++)
#pragma unroll
        for (int q = 0; q < 4; q++) acc[nt][q] = 0.f;

    // issue chunk c's loads into stage s
    auto issue = [&](int c, int s) {
        const float* xs_ = xrow_src + c * KC2 + xfo;
        uint32_t xd = sx_base + (uint32_t)(((s * GROWS + xr) * XSTR + xfo) * 4);
#pragma unroll
        for (int i = 0; i < 4; i++) cp_async16(xd + 16 * i, xs_ + 4 * i, xsz);
        const float* ws_ = wrow_src + c * KC2 + wfo;
        uint32_t wd = sw_base + (uint32_t)(((s * DOUT + wn) * XSTR + wfo) * 4);
#pragma unroll
        for (int i = 0; i < 2; i++) cp_async16(wd + 16 * i, ws_ + 4 * i, 16);
        asm volatile("cp.async.commit_group;");
    };

    issue(0, 0);
    issue(1, 1);

    for (int c = 0; c < DIN / KC2; c++) {
        const int s = c & 1;
        if (c < DIN / KC2 - 1) asm volatile("cp.async.wait_group 1;");
        else                   asm volatile("cp.async.wait_group 0;");
        __syncthreads();

#pragma unroll
        for (int ks = 0; ks < 2; ks++) {
            const int kb = ks * 16 + 2 * tg;
            const float* x0 = sx + (s * GROWS + wrow + gid)     * XSTR;
            const float* x1 = sx + (s * GROWS + wrow + gid + 8) * XSTR;
            float2 t0 = *(const float2*)(x0 + kb);
            float2 t1 = *(const float2*)(x1 + kb);
            float2 t2 = *(const float2*)(x0 + kb + 8);
            float2 t3 = *(const float2*)(x1 + kb + 8);
            uint32_t a[4];
            a[0] = f2h2(t0.x, t0.y); a[1] = f2h2(t1.x, t1.y);
            a[2] = f2h2(t2.x, t2.y); a[3] = f2h2(t3.x, t3.y);
#pragma unroll
            for (int nt = 0; nt < 8; nt++) {
                const float* wr = sw + (s * DOUT + nt * 8 + gid) * XSTR;
                float2 u0 = *(const float2*)(wr + kb);
                float2 u1 = *(const float2*)(wr + kb + 8);
                mma_16816(acc[nt], a, f2h2(u0.x, u0.y), f2h2(u1.x, u1.y));
            }
        }
        __syncthreads();
        if (c + 2 < DIN / KC2) issue(c + 2, s);
    }

    // ---- epilogue: bias + relu -> g_hh and g_zhA (fp16) ----
    int r0 = row0 + wrow + gid;
    int r1 = r0 + 8;
#pragma unroll
    for (int nt = 0; nt < 8; nt++) {
        int cn = nt * 8 + 2 * tg;
        float b0v = b[cn], b1v = b[cn + 1];
        int ci = (cn >> 1);
        if (r0 < NN) {
            __half2 v = __floats2half2_rn(fmaxf(acc[nt][0] + b0v, 0.f),
                                          fmaxf(acc[nt][1] + b1v, 0.f));
            ((__half2*)g_hh )[r0 * 32 + ci] = v;
            ((__half2*)g_zhA)[r0 * 32 + ci] = v;
        }
        if (r1 < NN) {
            __half2 v = __floats2half2_rn(fmaxf(acc[nt][2] + b0v, 0.f),
                                          fmaxf(acc[nt][3] + b1v, 0.f));
            ((__half2*)g_hh )[r1 * 32 + ci] = v;
            ((__half2*)g_zhA)[r1 * 32 + ci] = v;
        }
    }
}

// ---------------- degree count + scan + CSR ----------------
__global__ void deg_acc(const int* __restrict__ dst) {
    int e = blockIdx.x * blockDim.x + threadIdx.x;
    if (e < EE) atomicAdd(&g_cnt[dst[e]], 1);
}

__global__ __launch_bounds__(256) void scanA() {
    __shared__ int sh[256];
    int tid  = threadIdx.x;
    int base = blockIdx.x * SCAN_BS + tid * 4;
    int v[4];
#pragma unroll
    for (int q = 0; q < 4; q++) {
        int idx = base + q;
        v[q] = (idx < NN) ? g_cnt[idx] : 0;
        if (idx < NN) g_dinv[idx] = rsqrtf((float)(v[q] + 1));
    }
    int tsum = v[0] + v[1] + v[2] + v[3];
    sh[tid] = tsum;
    __syncthreads();
    for (int off = 1; off < 256; off <<= 1) {
        int x = (tid >= off) ? sh[tid - off] : 0;
        __syncthreads();
        sh[tid] += x;
        __syncthreads();
    }
    int run = sh[tid] - tsum;
#pragma unroll
    for (int q = 0; q < 4; q++) {
        int idx = base + q;
        if (idx < NN) g_rowtmp[idx] = run;
        run += v[q];
    }
    if (tid == 255) g_blksum[blockIdx.x] = sh[255];
}

__global__ __launch_bounds__(128) void scanB() {
    __shared__ int sh[128];
    int tid = threadIdx.x;
    int v = (tid < SCAN_NB) ? g_blksum[tid] : 0;
    sh[tid] = v;
    __syncthreads();
    for (int off = 1; off < 128; off <<= 1) {
        int x = (tid >= off) ? sh[tid - off] : 0;
        __syncthreads();
        sh[tid] += x;
        __syncthreads();
    }
    g_blkoff[tid] = sh[tid] - v;
}

__global__ void scanC() {
    int i = blockIdx.x * blockDim.x + threadIdx.x;
    if (i < NN) g_rowstart[i] = g_rowtmp[i] + g_blkoff[i / SCAN_BS];
    if (i == 0) g_rowstart[NN] = EE;
}

__global__ void csr_fill(const int* __restrict__ src, const int* __restrict__ dst) {
    int e = blockIdx.x * blockDim.x + threadIdx.x;
    if (e >= EE) return;
    int d = dst[e];
    int s = src[e];
    int pos = g_rowstart[d] + atomicAdd(&g_cursor[d], 1);
    float w = 0.9f * g_dinv[s] * g_dinv[d];
    g_epk[pos] = make_int2(s, __float_as_int(w));
}

// ---------------- fused APPNP step (R12-proven) ------------------------
#define WPB 8
__global__ __launch_bounds__(WPB * 32) void appnp_step(int in_sel, int out_sel,
                                                       float* __restrict__ ext) {
    int warp = threadIdx.x >> 5;
    int lane = threadIdx.x & 31;
    int node = blockIdx.x * WPB + warp;
    if (node >= NN) return;

    const __half2* zin = (in_sel == 0) ? (const __half2*)g_zhA
                                       : (const __half2*)g_zhB;

    float di = g_dinv[node];
    float sw = 0.9f * di * di;
    int   ri = node * 32 + lane;

    float2 hd = __half22float2(((const __half2*)g_hh)[ri]);
    float2 zd = __half22float2(zin[ri]);
    float accx = ALPHA * hd.x + sw * zd.x;
    float accy = ALPHA * hd.y + sw * zd.y;

    int j  = g_rowstart[node];
    int j1 = g_rowstart[node + 1];

    for (; j + 8 <= j1; j += 8) {
        int2 p[8];
#pragma unroll
        for (int q = 0; q < 8; q++) p[q] = g_epk[j + q];
        float2 a[8];
#pragma unroll
        for (int q = 0; q < 8; q++) a[q] = __half22float2(zin[p[q].x * 32 + lane]);
#pragma unroll
        for (int q = 0; q < 8; q++) {
            float w = __int_as_float(p[q].y);
            accx += w * a[q].x;
            accy += w * a[q].y;
        }
    }
    for (; j < j1; j++) {
        int2  p = g_epk[j];
        float w = __int_as_float(p.y);
        float2 a = __half22float2(zin[p.x * 32 + lane]);
        accx += w * a.x;
        accy += w * a.y;
    }

    if (out_sel == 3) {
        float2 o; o.x = accx; o.y = accy;
        ((float2*)ext)[ri] = o;
    } else {
        __half2* zout = (out_sel == 0) ? (__half2*)g_zhA : (__half2*)g_zhB;
        zout[ri] = __floats2half2_rn(accx, accy);
    }
}

// ---------------- launch (forked graph: GEMM || CSR build) -------------
extern "C" void kernel_launch(void* const* d_in, const int* in_sizes, int n_in,
                              void* d_out, int out_size) {
    const float* x  = (const float*)d_in[0];
    const int*   ei = (const int*)  d_in[1];
    const float* W  = (const float*)d_in[2];
    const float* b  = (const float*)d_in[3];
    float* out = (float*)d_out;

    const int* se = ei;        // src row
    const int* de = ei + EE;   // dst row

    static cudaStream_t s2 = nullptr;
    static cudaEvent_t  evFork = nullptr, evJoin = nullptr;
    static void* cnt_addr = nullptr;
    static void* cur_addr = nullptr;
    if (s2 == nullptr) {
        cudaStreamCreateWithFlags(&s2, cudaStreamNonBlocking);
        cudaEventCreateWithFlags(&evFork, cudaEventDisableTiming);
        cudaEventCreateWithFlags(&evJoin, cudaEventDisableTiming);
        cudaGetSymbolAddress(&cnt_addr, g_cnt);
        cudaGetSymbolAddress(&cur_addr, g_cursor);
        cudaFuncSetAttribute(gemm_relu,
                             cudaFuncAttributeMaxDynamicSharedMemorySize,
                             GEMM_SMEM);
    }

    // fork: GEMM on s2, concurrent with CSR build chain
    cudaEventRecord(evFork, 0);
    cudaStreamWaitEvent(s2, evFork, 0);
    gemm_relu<<<(NN + GROWS - 1) / GROWS, 256, GEMM_SMEM, s2>>>(x, W, b);
    cudaEventRecord(evJoin, s2);

    // origin stream: degree + scan + CSR build
    cudaMemsetAsync(cnt_addr, 0, NN * sizeof(int), 0);
    cudaMemsetAsync(cur_addr, 0, NN * sizeof(int), 0);
    deg_acc<<<(EE + 255) / 256, 256>>>(de);
    scanA<<<SCAN_NB, 256>>>();
    scanB<<<1, 128>>>();
    scanC<<<(NN + 255) / 256, 256>>>();
    csr_fill<<<(EE + 255) / 256, 256>>>(se, de);

    cudaStreamWaitEvent(0, evJoin, 0);

    // K-step APPNP propagation; ping-pong A<->B; last step -> d_out fp32
    const int step_grid = (NN + WPB - 1) / WPB;
    for (int k = 0; k < KPROP; k++) {
        int in_sel  = k & 1;
        int out_sel = (k == KPROP - 1) ? 3 : 1 - (k & 1);
        appnp_step<<<step_grid, WPB * 32>>>(in_sel, out_sel, out);
    }
}

// round 17
// speedup vs baseline: 1.2420x; 1.0174x over previous
#include <cuda_runtime.h>
#include <cuda_fp16.h>
#include <cstdint>
#include <math.h>

// ---------------- problem constants ----------------
#define NN    100000
#define EE    1600000
#define DIN   256
#define DOUT  64
#define KPROP 10
#define ALPHA 0.1f

// ---------------- static device scratch ----------------
__device__ __half g_hh [(size_t)NN * DOUT];   // h in fp16
__device__ __half g_zhA[(size_t)NN * DOUT];
__device__ __half g_zhB[(size_t)NN * DOUT];
__device__ float  g_dinv[NN];

__device__ int   g_cnt   [NN];
__device__ int   g_cursor[NN];
__device__ int   g_rowstart[NN + 1];
__device__ int2  g_epk[EE + 16];     // packed (src idx, weight bits)
__device__ int   g_blksum[128];

#define SCAN_BS  1024
#define SCAN_NB  ((NN + SCAN_BS - 1) / SCAN_BS)   // 98
__device__ int g_rowtmp[NN];

// ---------------- helpers ----------------
__device__ __forceinline__ uint32_t f2h2(float a, float b) {
    __half2 h = __floats2half2_rn(a, b);
    return *(uint32_t*)&h;
}

__device__ __forceinline__ void mma_16816(float* c, const uint32_t* a,
                                          uint32_t b0, uint32_t b1) {
    asm volatile(
        "mma.sync.aligned.m16n8k16.row.col.f32.f16.f16.f32 "
        "{%0,%1,%2,%3}, {%4,%5,%6,%7}, {%8,%9}, {%0,%1,%2,%3};"
        : "+f"(c[0]), "+f"(c[1]), "+f"(c[2]), "+f"(c[3])
        : "r"(a[0]), "r"(a[1]), "r"(a[2]), "r"(a[3]), "r"(b0), "r"(b1));
}

__device__ __forceinline__ void ldsm_x4(uint32_t* r, uint32_t addr) {
    asm volatile("ldmatrix.sync.aligned.m8n8.x4.shared.b16 {%0,%1,%2,%3}, [%4];"
                 : "=r"(r[0]), "=r"(r[1]), "=r"(r[2]), "=r"(r[3]) : "r"(addr));
}

// ---------------- tensor-core GEMM + bias + ReLU (R8-proven) -----------
#define GROWS 128
#define XPAD  72   // half stride; row pitch 144B

__global__ __launch_bounds__(256) void gemm_relu(
    const float* __restrict__ x, const float* __restrict__ W,
    const float* __restrict__ b)
{
    __shared__ __half xs[GROWS * XPAD];   // 18.4 KB
    __shared__ __half ws[DOUT * XPAD];    //  9.2 KB

    const int tid  = threadIdx.x;
    const int warp = tid >> 5;
    const int lane = tid & 31;
    const int gid  = lane >> 2;
    const int tg   = lane & 3;
    const int row0 = blockIdx.x * GROWS;
    const int wrow = warp * 16;

    const uint32_t xs_base = (uint32_t)__cvta_generic_to_shared(xs);
    const uint32_t ws_base = (uint32_t)__cvta_generic_to_shared(ws);

    const int arow    = wrow + (lane & 15);
    const int acolsel = (lane >> 4) << 3;
    const int browsel = (((lane >> 4) & 1) << 3) + (lane & 7);
    const int bcolsel = ((lane >> 3) & 1) << 3;

    float acc[8][4];
#pragma unroll
    for (int nt = 0; nt < 8; nt++)
#pragma unroll
        for (int q = 0; q < 4; q++) acc[nt][q] = 0.f;

    for (int kc = 0; kc < DIN / 64; kc++) {
        const int k0 = kc * 64;
        __syncthreads();
        {
            int n  = tid >> 2;
            int kq = (tid & 3) * 16;
            const float4* wsrc = (const float4*)(W + (size_t)n * DIN + k0 + kq);
            uint4* d = (uint4*)&ws[n * XPAD + kq];
#pragma unroll
            for (int i = 0; i < 2; i++) {
                float4 v0 = wsrc[2 * i], v1 = wsrc[2 * i + 1];
                uint4 u;
                u.x = f2h2(v0.x, v0.y); u.y = f2h2(v0.z, v0.w);
                u.z = f2h2(v1.x, v1.y); u.w = f2h2(v1.z, v1.w);
                d[i] = u;
            }
        }
        {
            int r  = tid >> 1;
            int kq = (tid & 1) * 32;
            int gr = row0 + r;
            uint4* d = (uint4*)&xs[r * XPAD + kq];
            if (gr < NN) {
                const float4* xsrc = (const float4*)(x + (size_t)gr * DIN + k0 + kq);
#pragma unroll
                for (int i = 0; i < 4; i++) {
                    float4 v0 = xsrc[2 * i], v1 = xsrc[2 * i + 1];
                    uint4 u;
                    u.x = f2h2(v0.x, v0.y); u.y = f2h2(v0.z, v0.w);
                    u.z = f2h2(v1.x, v1.y); u.w = f2h2(v1.z, v1.w);
                    d[i] = u;
                }
            } else {
                uint4 u = make_uint4(0, 0, 0, 0);
#pragma unroll
                for (int i = 0; i < 4; i++) d[i] = u;
            }
        }
        __syncthreads();

#pragma unroll
        for (int ks = 0; ks < 4; ks++) {
            uint32_t a[4];
            ldsm_x4(a, xs_base + (uint32_t)((arow * XPAD + ks * 16 + acolsel) * 2));
#pragma unroll
            for (int p = 0; p < 4; p++) {
                uint32_t bb[4];
                int brow = p * 16 + browsel;
                ldsm_x4(bb, ws_base + (uint32_t)((brow * XPAD + ks * 16 + bcolsel) * 2));
                mma_16816(acc[2 * p],     a, bb[0], bb[1]);
                mma_16816(acc[2 * p + 1], a, bb[2], bb[3]);
            }
        }
    }

    int r0 = row0 + wrow + gid;
    int r1 = r0 + 8;
#pragma unroll
    for (int nt = 0; nt < 8; nt++) {
        int cn = nt * 8 + 2 * tg;
        float b0v = b[cn], b1v = b[cn + 1];
        int ci = (cn >> 1);
        if (r0 < NN) {
            __half2 v = __floats2half2_rn(fmaxf(acc[nt][0] + b0v, 0.f),
                                          fmaxf(acc[nt][1] + b1v, 0.f));
            ((__half2*)g_hh )[r0 * 32 + ci] = v;
            ((__half2*)g_zhA)[r0 * 32 + ci] = v;
        }
        if (r1 < NN) {
            __half2 v = __floats2half2_rn(fmaxf(acc[nt][2] + b0v, 0.f),
                                          fmaxf(acc[nt][3] + b1v, 0.f));
            ((__half2*)g_hh )[r1 * 32 + ci] = v;
            ((__half2*)g_zhA)[r1 * 32 + ci] = v;
        }
    }
}

// ---------------- degree count + scan + CSR ----------------
__global__ void deg_acc(const int* __restrict__ dst) {
    int e = blockIdx.x * blockDim.x + threadIdx.x;
    if (e < EE) atomicAdd(&g_cnt[dst[e]], 1);
}

__global__ __launch_bounds__(256) void scanA() {
    __shared__ int sh[256];
    int tid  = threadIdx.x;
    int base = blockIdx.x * SCAN_BS + tid * 4;
    int v[4];
#pragma unroll
    for (int q = 0; q < 4; q++) {
        int idx = base + q;
        v[q] = (idx < NN) ? g_cnt[idx] : 0;
        if (idx < NN) g_dinv[idx] = rsqrtf((float)(v[q] + 1));
    }
    int tsum = v[0] + v[1] + v[2] + v[3];
    sh[tid] = tsum;
    __syncthreads();
    for (int off = 1; off < 256; off <<= 1) {
        int x = (tid >= off) ? sh[tid - off] : 0;
        __syncthreads();
        sh[tid] += x;
        __syncthreads();
    }
    int run = sh[tid] - tsum;
#pragma unroll
    for (int q = 0; q < 4; q++) {
        int idx = base + q;
        if (idx < NN) g_rowtmp[idx] = run;
        run += v[q];
    }
    if (tid == 255) g_blksum[blockIdx.x] = sh[255];
}

// merged scanB + scanC: per-thread offset from smem-cached block sums
__global__ __launch_bounds__(256) void scanBC() {
    __shared__ int sb[SCAN_NB];
    int i = blockIdx.x * blockDim.x + threadIdx.x;
    for (int t = threadIdx.x; t < SCAN_NB; t += blockDim.x) sb[t] = g_blksum[t];
    __syncthreads();
    if (i < NN) {
        int blk = i / SCAN_BS;
        int off = 0;
        for (int t = 0; t < blk; t++) off += sb[t];
        g_rowstart[i] = g_rowtmp[i] + off;
    }
    if (i == 0) g_rowstart[NN] = EE;
}

__global__ void csr_fill(const int* __restrict__ src, const int* __restrict__ dst) {
    int e = blockIdx.x * blockDim.x + threadIdx.x;
    if (e >= EE) return;
    int d = dst[e];
    int s = src[e];
    int pos = g_rowstart[d] + atomicAdd(&g_cursor[d], 1);
    float w = 0.9f * g_dinv[s] * g_dinv[d];
    g_epk[pos] = make_int2(s, __float_as_int(w));
}

// ---------------- fused APPNP step (R12 body + PDL prologue) -----------
#define WPB 8
__global__ __launch_bounds__(WPB * 32) void appnp_step(int in_sel, int out_sel,
                                                       float* __restrict__ ext) {
    int warp = threadIdx.x >> 5;
    int lane = threadIdx.x & 31;
    int node = blockIdx.x * WPB + warp;

    // ---- prologue: step-invariant data only (safe pre-dependency) ----
    float di = 0.f; float2 hd = make_float2(0.f, 0.f);
    int j = 0, j1 = 0, ri = 0;
    if (node < NN) {
        di = g_dinv[node];
        ri = node * 32 + lane;
        hd = __half22float2(((const __half2*)g_hh)[ri]);
        j  = g_rowstart[node];
        j1 = g_rowstart[node + 1];
    }

    // wait for predecessor grid's writes (z buffer) to be visible
    cudaGridDependencySynchronize();
    if (node >= NN) return;

    const __half2* zin = (in_sel == 0) ? (const __half2*)g_zhA
                                       : (const __half2*)g_zhB;
    float sw = 0.9f * di * di;
    float2 zd = __half22float2(zin[ri]);
    float accx = ALPHA * hd.x + sw * zd.x;
    float accy = ALPHA * hd.y + sw * zd.y;

    for (; j + 8 <= j1; j += 8) {
        int2 p[8];
#pragma unroll
        for (int q = 0; q < 8; q++) p[q] = g_epk[j + q];
        float2 a[8];
#pragma unroll
        for (int q = 0; q < 8; q++) a[q] = __half22float2(zin[p[q].x * 32 + lane]);
#pragma unroll
        for (int q = 0; q < 8; q++) {
            float w = __int_as_float(p[q].y);
            accx += w * a[q].x;
            accy += w * a[q].y;
        }
    }
    for (; j < j1; j++) {
        int2  p = g_epk[j];
        float w = __int_as_float(p.y);
        float2 a = __half22float2(zin[p.x * 32 + lane]);
        accx += w * a.x;
        accy += w * a.y;
    }

    if (out_sel == 3) {
        float2 o; o.x = accx; o.y = accy;
        ((float2*)ext)[ri] = o;
    } else {
        __half2* zout = (out_sel == 0) ? (__half2*)g_zhA : (__half2*)g_zhB;
        zout[ri] = __floats2half2_rn(accx, accy);
    }
}

// ---------------- launch (forked graph + PDL step chain) ---------------
extern "C" void kernel_launch(void* const* d_in, const int* in_sizes, int n_in,
                              void* d_out, int out_size) {
    const float* x  = (const float*)d_in[0];
    const int*   ei = (const int*)  d_in[1];
    const float* W  = (const float*)d_in[2];
    const float* b  = (const float*)d_in[3];
    float* out = (float*)d_out;

    const int* se = ei;        // src row
    const int* de = ei + EE;   // dst row

    static cudaStream_t s2 = nullptr;
    static cudaEvent_t  evFork = nullptr, evJoin = nullptr;
    static void* cnt_addr = nullptr;
    static void* cur_addr = nullptr;
    if (s2 == nullptr) {
        cudaStreamCreateWithFlags(&s2, cudaStreamNonBlocking);
        cudaEventCreateWithFlags(&evFork, cudaEventDisableTiming);
        cudaEventCreateWithFlags(&evJoin, cudaEventDisableTiming);
        cudaGetSymbolAddress(&cnt_addr, g_cnt);
        cudaGetSymbolAddress(&cur_addr, g_cursor);
    }

    // fork: GEMM on s2, concurrent with CSR build chain
    cudaEventRecord(evFork, 0);
    cudaStreamWaitEvent(s2, evFork, 0);
    gemm_relu<<<(NN + GROWS - 1) / GROWS, 256, 0, s2>>>(x, W, b);
    cudaEventRecord(evJoin, s2);

    // origin stream: degree + scan + CSR build
    cudaMemsetAsync(cnt_addr, 0, NN * sizeof(int), 0);
    cudaMemsetAsync(cur_addr, 0, NN * sizeof(int), 0);
    deg_acc<<<(EE + 255) / 256, 256>>>(de);
    scanA<<<SCAN_NB, 256>>>();
    scanBC<<<(NN + 255) / 256, 256>>>();
    csr_fill<<<(EE + 255) / 256, 256>>>(se, de);

    cudaStreamWaitEvent(0, evJoin, 0);

    // K-step APPNP propagation with programmatic dependent launches
    const int step_grid = (NN + WPB - 1) / WPB;
    for (int k = 0; k < KPROP; k++) {
        int in_sel  = k & 1;
        int out_sel = (k == KPROP - 1) ? 3 : 1 - (k & 1);

        cudaLaunchConfig_t cfg = {};
        cfg.gridDim  = dim3((unsigned)step_grid);
        cfg.blockDim = dim3(WPB * 32);
        cfg.dynamicSmemBytes = 0;
        cfg.stream = 0;
        cudaLaunchAttribute attr[1];
        attr[0].id = cudaLaunchAttributeProgrammaticStreamSerialization;
        attr[0].val.programmaticStreamSerializationAllowed = 1;
        cfg.attrs = attr;
        cfg.numAttrs = 1;
        cudaLaunchKernelEx(&cfg, appnp_step, in_sel, out_sel, out);
    }
}